// round 14
// baseline (speedup 1.0000x reference)
#include <cuda_runtime.h>
#include <cuda_bf16.h>

#define Bb    256
#define Ssz   1000
#define Esz   512
#define Hh    8
#define DFFsz 2048
#define SPLITK 16
#define IDXPAD 1024
#define NEG_BIG (-1e30f)

// Scratch (device globals: allocation-free)
__device__ float g_glimpse[Bb * Esz];
__device__ float g_T[Bb * DFFsz];
__device__ float g_part[SPLITK * Bb * Esz];
__device__ int   g_idx[Bb * IDXPAD];
__device__ int   g_cnt[Bb];

// ---------------------------------------------------------------------------
// Kernel 0: deterministic ordered compaction of active mask indices.
// Pads to a multiple of 64 (8 rows x 8 warps in attn).
// ---------------------------------------------------------------------------
__global__ __launch_bounds__(256) void compact_kernel(
    const int* __restrict__ mask, int* __restrict__ idx, int* __restrict__ cnt)
{
    __shared__ int wsum[8];
    __shared__ int woff[8];
    const int b    = blockIdx.x;
    const int tid  = threadIdx.x;
    const int lane = tid & 31;
    const int wid  = tid >> 5;
    const int* mb = mask + b * Ssz;
    int* ib = idx + b * IDXPAD;

    const int s0 = tid * 4;
    int m[4];
    int c = 0;
    #pragma unroll
    for (int j = 0; j < 4; j++) {
        int s = s0 + j;
        m[j] = (s < Ssz) ? (mb[s] != 0) : 0;
        c += m[j];
    }
    int inc = c;
    #pragma unroll
    for (int o = 1; o < 32; o <<= 1) {
        int v = __shfl_up_sync(0xffffffffu, inc, o);
        if (lane >= o) inc += v;
    }
    if (lane == 31) wsum[wid] = inc;
    __syncthreads();
    if (tid == 0) {
        int acc = 0;
        #pragma unroll
        for (int w = 0; w < 8; w++) { woff[w] = acc; acc += wsum[w]; }
        cnt[b] = acc;
    }
    __syncthreads();
    int off = woff[wid] + inc - c;
    #pragma unroll
    for (int j = 0; j < 4; j++) {
        if (m[j]) ib[off++] = s0 + j;
    }
    __syncthreads();
    const int total = woff[7] + wsum[7];
    const int pc = (total + 63) & ~63;
    const int first = ib[0];
    for (int i = total + tid; i < pc; i += 256) ib[i] = first;
}

// ---------------------------------------------------------------------------
// Kernel 1: attention over COMPACTED active rows.
// Grid (4 E-chunks, nB), 256 threads (8 warps). 2 heads per CTA. 8-row unroll.
// (16-row variant regressed: register pressure — 8 is the empirical optimum.)
// ---------------------------------------------------------------------------
__global__ __launch_bounds__(256) void attn_kernel(
    const float* __restrict__ q,
    const float* __restrict__ kk,
    const float* __restrict__ vv,
    const int*   __restrict__ idx,
    const int*   __restrict__ cnt,
    float* __restrict__ glimpse,
    int b0)
{
    __shared__ float qs[128];
    __shared__ int   idx_s[IDXPAD];
    __shared__ float sc[2][IDXPAD];
    __shared__ float wacc[8][128];
    __shared__ float red[2][4];
    __shared__ float invs[2];

    const int hp   = blockIdx.x;
    const int b    = b0 + blockIdx.y;
    const int tid  = threadIdx.x;
    const int wid  = tid >> 5;
    const int lane = tid & 31;
    const int e0   = hp * 128;

    const int cn = cnt[b];
    const int pc = (cn + 63) & ~63;

    if (tid < 128) qs[tid] = q[b * Esz + e0 + tid];
    {
        const int* ib = idx + b * IDXPAD;
        for (int i = tid; i < pc; i += 256) idx_s[i] = ib[i];
    }
    __syncthreads();

    const float4* q4 = (const float4*)qs;
    const float* kb = kk + (size_t)b * Ssz * Esz + e0;
    const float* vb = vv + (size_t)b * Ssz * Esz + e0;

    // ---- Pass A ----
    {
        const float4 qq = q4[lane];
        for (int i0 = wid * 8; i0 < pc; i0 += 64) {
            int s0 = idx_s[i0 + 0], s1 = idx_s[i0 + 1];
            int s2 = idx_s[i0 + 2], s3 = idx_s[i0 + 3];
            int s4 = idx_s[i0 + 4], s5 = idx_s[i0 + 5];
            int s6 = idx_s[i0 + 6], s7 = idx_s[i0 + 7];
            float4 k0 = __ldcs((const float4*)(kb + (size_t)s0 * Esz) + lane);
            float4 k1 = __ldcs((const float4*)(kb + (size_t)s1 * Esz) + lane);
            float4 k2 = __ldcs((const float4*)(kb + (size_t)s2 * Esz) + lane);
            float4 k3 = __ldcs((const float4*)(kb + (size_t)s3 * Esz) + lane);
            float4 k4 = __ldcs((const float4*)(kb + (size_t)s4 * Esz) + lane);
            float4 k5 = __ldcs((const float4*)(kb + (size_t)s5 * Esz) + lane);
            float4 k6 = __ldcs((const float4*)(kb + (size_t)s6 * Esz) + lane);
            float4 k7 = __ldcs((const float4*)(kb + (size_t)s7 * Esz) + lane);
            float p0 = k0.x * qq.x + k0.y * qq.y + k0.z * qq.z + k0.w * qq.w;
            float p1 = k1.x * qq.x + k1.y * qq.y + k1.z * qq.z + k1.w * qq.w;
            float p2 = k2.x * qq.x + k2.y * qq.y + k2.z * qq.z + k2.w * qq.w;
            float p3 = k3.x * qq.x + k3.y * qq.y + k3.z * qq.z + k3.w * qq.w;
            float p4 = k4.x * qq.x + k4.y * qq.y + k4.z * qq.z + k4.w * qq.w;
            float p5 = k5.x * qq.x + k5.y * qq.y + k5.z * qq.z + k5.w * qq.w;
            float p6 = k6.x * qq.x + k6.y * qq.y + k6.z * qq.z + k6.w * qq.w;
            float p7 = k7.x * qq.x + k7.y * qq.y + k7.z * qq.z + k7.w * qq.w;
            #pragma unroll
            for (int o = 1; o < 16; o <<= 1) {
                p0 += __shfl_xor_sync(0xffffffffu, p0, o);
                p1 += __shfl_xor_sync(0xffffffffu, p1, o);
                p2 += __shfl_xor_sync(0xffffffffu, p2, o);
                p3 += __shfl_xor_sync(0xffffffffu, p3, o);
                p4 += __shfl_xor_sync(0xffffffffu, p4, o);
                p5 += __shfl_xor_sync(0xffffffffu, p5, o);
                p6 += __shfl_xor_sync(0xffffffffu, p6, o);
                p7 += __shfl_xor_sync(0xffffffffu, p7, o);
            }
            if ((lane & 15) == 0) {
                int h = lane >> 4;
                sc[h][i0]     = p0 * 0.125f;
                sc[h][i0 + 1] = p1 * 0.125f;
                sc[h][i0 + 2] = p2 * 0.125f;
                sc[h][i0 + 3] = p3 * 0.125f;
                sc[h][i0 + 4] = p4 * 0.125f;
                sc[h][i0 + 5] = p5 * 0.125f;
                sc[h][i0 + 6] = p6 * 0.125f;
                sc[h][i0 + 7] = p7 * 0.125f;
            }
        }
    }
    __syncthreads();

    // ---- Softmax over [0, cn) ----
    {
        const int h = wid >> 2;
        const int sub = wid & 3;
        const int t = sub * 32 + lane;

        float m = NEG_BIG;
        for (int i = t; i < cn; i += 128) m = fmaxf(m, sc[h][i]);
        #pragma unroll
        for (int o = 16; o; o >>= 1) m = fmaxf(m, __shfl_xor_sync(0xffffffffu, m, o));
        if (lane == 0) red[h][sub] = m;
        __syncthreads();
        m = fmaxf(fmaxf(red[h][0], red[h][1]), fmaxf(red[h][2], red[h][3]));
        __syncthreads();

        float sum = 0.f;
        for (int i = t; i < cn; i += 128) {
            float e = __expf(sc[h][i] - m);
            sc[h][i] = e;
            sum += e;
        }
        #pragma unroll
        for (int o = 16; o; o >>= 1) sum += __shfl_xor_sync(0xffffffffu, sum, o);
        if (lane == 0) red[h][sub] = sum;
        __syncthreads();
        if (t == 0)
            invs[h] = 1.0f / (red[h][0] + red[h][1] + red[h][2] + red[h][3]);
    }
    for (int i = cn + tid; i < pc; i += 256) { sc[0][i] = 0.f; sc[1][i] = 0.f; }
    __syncthreads();

    // ---- Pass B ----
    {
        const int h = lane >> 4;
        float a0 = 0.f, a1 = 0.f, a2 = 0.f, a3 = 0.f;
        for (int i0 = wid * 8; i0 < pc; i0 += 64) {
            int s0 = idx_s[i0 + 0], s1 = idx_s[i0 + 1];
            int s2 = idx_s[i0 + 2], s3 = idx_s[i0 + 3];
            int s4 = idx_s[i0 + 4], s5 = idx_s[i0 + 5];
            int s6 = idx_s[i0 + 6], s7 = idx_s[i0 + 7];
            float4 v0 = __ldcs((const float4*)(vb + (size_t)s0 * Esz) + lane);
            float4 v1 = __ldcs((const float4*)(vb + (size_t)s1 * Esz) + lane);
            float4 v2 = __ldcs((const float4*)(vb + (size_t)s2 * Esz) + lane);
            float4 v3 = __ldcs((const float4*)(vb + (size_t)s3 * Esz) + lane);
            float4 v4 = __ldcs((const float4*)(vb + (size_t)s4 * Esz) + lane);
            float4 v5 = __ldcs((const float4*)(vb + (size_t)s5 * Esz) + lane);
            float4 v6 = __ldcs((const float4*)(vb + (size_t)s6 * Esz) + lane);
            float4 v7 = __ldcs((const float4*)(vb + (size_t)s7 * Esz) + lane);
            float p0 = sc[h][i0];
            float p1 = sc[h][i0 + 1];
            float p2 = sc[h][i0 + 2];
            float p3 = sc[h][i0 + 3];
            float p4 = sc[h][i0 + 4];
            float p5 = sc[h][i0 + 5];
            float p6 = sc[h][i0 + 6];
            float p7 = sc[h][i0 + 7];
            a0 += p0 * v0.x + p1 * v1.x + p2 * v2.x + p3 * v3.x
                + p4 * v4.x + p5 * v5.x + p6 * v6.x + p7 * v7.x;
            a1 += p0 * v0.y + p1 * v1.y + p2 * v2.y + p3 * v3.y
                + p4 * v4.y + p5 * v5.y + p6 * v6.y + p7 * v7.y;
            a2 += p0 * v0.z + p1 * v1.z + p2 * v2.z + p3 * v3.z
                + p4 * v4.z + p5 * v5.z + p6 * v6.z + p7 * v7.z;
            a3 += p0 * v0.w + p1 * v1.w + p2 * v2.w + p3 * v3.w
                + p4 * v4.w + p5 * v5.w + p6 * v6.w + p7 * v7.w;
        }
        float inv = invs[h];
        ((float4*)wacc[wid])[lane] = make_float4(a0 * inv, a1 * inv, a2 * inv, a3 * inv);
    }
    __syncthreads();

    if (tid < 128) {
        float r = 0.f;
        #pragma unroll
        for (int w = 0; w < 8; w++) r += wacc[w][tid];
        glimpse[b * Esz + e0 + tid] = r + qs[tid];
    }
}

// ---------------------------------------------------------------------------
// Double-buffered fp32 GEMM. EPI 0: relu(x+bias) -> C ; EPI 2: raw -> C
// blockIdx.z = split-K slice: A += z*K (cols), B += z*K*N, C += z*zc.
// ---------------------------------------------------------------------------
template <int BM, int BN, int BK, int TM, int TN, int NT, int EPI>
__global__ __launch_bounds__(NT) void gemm_kernel(
    const float* __restrict__ A, const float* __restrict__ B,
    float* __restrict__ C, const float* __restrict__ bias,
    int M, int N, int K, int lda, size_t zc)
{
    constexpr int PAD = 4;
    __shared__ float As[2][BK][BM + PAD];   // transposed [k][m]
    __shared__ float Bs[2][BK][BN];

    constexpr int TX = BN / TN;
    constexpr int KQ = BK / 4;
    constexpr int NQ = BN / 4;
    constexpr int AV = (BM * KQ) / NT;
    constexpr int BV = (BK * NQ) / NT;
    static_assert(AV * NT == BM * KQ && BV * NT == BK * NQ, "loaders");
    static_assert(TX * (BM / TM) == NT, "tiling");

    const int tid = threadIdx.x;
    const int tx = tid % TX;
    const int ty = tid / TX;
    const int m0 = blockIdx.y * BM;
    const int n0 = blockIdx.x * BN;
    const int z  = blockIdx.z;

    A += (size_t)z * K;
    B += (size_t)z * K * N;
    C += (size_t)z * zc;

    float acc[TM][TN];
    #pragma unroll
    for (int i = 0; i < TM; i++)
        #pragma unroll
        for (int j = 0; j < TN; j++) acc[i][j] = 0.f;

    #pragma unroll
    for (int r = 0; r < AV; r++) {
        int u = tid + r * NT, m = u / KQ, kq = u % KQ;
        float4 a = *(const float4*)&A[(size_t)(m0 + m) * lda + kq * 4];
        As[0][kq * 4 + 0][m] = a.x; As[0][kq * 4 + 1][m] = a.y;
        As[0][kq * 4 + 2][m] = a.z; As[0][kq * 4 + 3][m] = a.w;
    }
    #pragma unroll
    for (int r = 0; r < BV; r++) {
        int u = tid + r * NT, kr = u / NQ, nq = u % NQ;
        *(float4*)&Bs[0][kr][nq * 4] = *(const float4*)&B[(size_t)kr * N + n0 + nq * 4];
    }
    __syncthreads();

    const int nk = K / BK;
    float4 pa[AV], pb[BV];

    for (int t = 0; t < nk; t++) {
        const int cur = t & 1;
        if (t + 1 < nk) {
            const int k0 = (t + 1) * BK;
            #pragma unroll
            for (int r = 0; r < AV; r++) {
                int u = tid + r * NT, m = u / KQ, kq = u % KQ;
                pa[r] = *(const float4*)&A[(size_t)(m0 + m) * lda + k0 + kq * 4];
            }
            #pragma unroll
            for (int r = 0; r < BV; r++) {
                int u = tid + r * NT, kr = u / NQ, nq = u % NQ;
                pb[r] = *(const float4*)&B[(size_t)(k0 + kr) * N + n0 + nq * 4];
            }
        }
        #pragma unroll
        for (int k = 0; k < BK; k++) {
            float ra[TM], rb[TN];
            if constexpr (TM == 4) {
                float4 t4 = *(const float4*)&As[cur][k][ty * 4];
                ra[0] = t4.x; ra[1] = t4.y; ra[2] = t4.z; ra[3] = t4.w;
            } else {
                float2 t2 = *(const float2*)&As[cur][k][ty * 2];
                ra[0] = t2.x; ra[1] = t2.y;
            }
            if constexpr (TN == 4) {
                float4 t4 = *(const float4*)&Bs[cur][k][tx * 4];
                rb[0] = t4.x; rb[1] = t4.y; rb[2] = t4.z; rb[3] = t4.w;
            } else {
                float2 t2 = *(const float2*)&Bs[cur][k][tx * 2];
                rb[0] = t2.x; rb[1] = t2.y;
            }
            #pragma unroll
            for (int i = 0; i < TM; i++)
                #pragma unroll
                for (int j = 0; j < TN; j++) acc[i][j] += ra[i] * rb[j];
        }
        if (t + 1 < nk) {
            const int nb = cur ^ 1;
            #pragma unroll
            for (int r = 0; r < AV; r++) {
                int u = tid + r * NT, m = u / KQ, kq = u % KQ;
                As[nb][kq * 4 + 0][m] = pa[r].x; As[nb][kq * 4 + 1][m] = pa[r].y;
                As[nb][kq * 4 + 2][m] = pa[r].z; As[nb][kq * 4 + 3][m] = pa[r].w;
            }
            #pragma unroll
            for (int r = 0; r < BV; r++) {
                int u = tid + r * NT, kr = u / NQ, nq = u % NQ;
                *(float4*)&Bs[nb][kr][nq * 4] = pb[r];
            }
        }
        __syncthreads();
    }

    #pragma unroll
    for (int i = 0; i < TM; i++) {
        const int m = m0 + ty * TM + i;
        if constexpr (EPI == 0) {
            if constexpr (TN == 4) {
                float4 bs4 = *(const float4*)&bias[n0 + tx * 4];
                float4 o;
                o.x = fmaxf(acc[i][0] + bs4.x, 0.f);
                o.y = fmaxf(acc[i][1] + bs4.y, 0.f);
                o.z = fmaxf(acc[i][2] + bs4.z, 0.f);
                o.w = fmaxf(acc[i][3] + bs4.w, 0.f);
                *(float4*)&C[(size_t)m * N + n0 + tx * 4] = o;
            } else {
                float2 bs2 = *(const float2*)&bias[n0 + tx * 2];
                float2 o;
                o.x = fmaxf(acc[i][0] + bs2.x, 0.f);
                o.y = fmaxf(acc[i][1] + bs2.y, 0.f);
                *(float2*)&C[(size_t)m * N + n0 + tx * 2] = o;
            }
        } else {
            if constexpr (TN == 4) {
                float4 o;
                o.x = acc[i][0]; o.y = acc[i][1]; o.z = acc[i][2]; o.w = acc[i][3];
                *(float4*)&C[(size_t)m * N + n0 + tx * 4] = o;
            } else {
                float2 o; o.x = acc[i][0]; o.y = acc[i][1];
                *(float2*)&C[(size_t)m * N + n0 + tx * 2] = o;
            }
        }
    }
}

// ---------------------------------------------------------------------------
// Kernel 3: fused split-K reduce + pointer logits for batches [b0, ...).
// ---------------------------------------------------------------------------
__global__ __launch_bounds__(512) void logits_kernel(
    const float* __restrict__ part,
    const float* __restrict__ glimpse,
    const float* __restrict__ b2,
    const float* __restrict__ lk,
    float* __restrict__ out,
    int b0)
{
    __shared__ float gs[Esz];
    const int b    = b0 + blockIdx.y;
    const int tid  = threadIdx.x;
    const int wid  = tid >> 5;
    const int lane = tid & 31;

    {
        const int e = tid;
        float v = glimpse[b * Esz + e] + b2[e];
        #pragma unroll
        for (int z = 0; z < SPLITK; z++)
            v += part[(size_t)z * Bb * Esz + b * Esz + e];
        gs[e] = v;
    }
    __syncthreads();

    const float4* g4 = (const float4*)gs;
    const int s0 = blockIdx.x * 500;
    const float rscale = 0.04419417382415922f;  // 1/sqrt(512)

    for (int g = wid; g < 125; g += 16) {
        const int s = s0 + g * 4;
        const float4* r = (const float4*)(lk + ((size_t)b * Ssz + s) * Esz) + lane;
        float p0 = 0.f, p1 = 0.f, p2 = 0.f, p3 = 0.f;
        #pragma unroll
        for (int j = 0; j < 4; j++) {
            float4 qv = g4[j * 32 + lane];
            float4 a0 = __ldcs(r + j * 32);
            float4 a1 = __ldcs(r + 128 + j * 32);
            float4 a2 = __ldcs(r + 256 + j * 32);
            float4 a3 = __ldcs(r + 384 + j * 32);
            p0 += a0.x * qv.x + a0.y * qv.y + a0.z * qv.z + a0.w * qv.w;
            p1 += a1.x * qv.x + a1.y * qv.y + a1.z * qv.z + a1.w * qv.w;
            p2 += a2.x * qv.x + a2.y * qv.y + a2.z * qv.z + a2.w * qv.w;
            p3 += a3.x * qv.x + a3.y * qv.y + a3.z * qv.z + a3.w * qv.w;
        }
        #pragma unroll
        for (int o = 16; o; o >>= 1) {
            p0 += __shfl_xor_sync(0xffffffffu, p0, o);
            p1 += __shfl_xor_sync(0xffffffffu, p1, o);
            p2 += __shfl_xor_sync(0xffffffffu, p2, o);
            p3 += __shfl_xor_sync(0xffffffffu, p3, o);
        }
        if (lane == 0) {
            float4 o4 = make_float4(p0 * rscale, p1 * rscale, p2 * rscale, p3 * rscale);
            *(float4*)&out[(size_t)b * Ssz + s] = o4;
        }
    }
}

// ---------------------------------------------------------------------------
// Host: compact -> 2-half pipeline with balanced tail-fill.
// ---------------------------------------------------------------------------
extern "C" void kernel_launch(void* const* d_in, const int* in_sizes, int n_in,
                              void* d_out, int out_size)
{
    const float* query    = (const float*)d_in[0];
    const float* key      = (const float*)d_in[1];
    const float* value    = (const float*)d_in[2];
    const float* logitkey = (const float*)d_in[3];
    const int*   mask     = (const int*)  d_in[4];
    const float* W1       = (const float*)d_in[5];
    const float* b1       = (const float*)d_in[6];
    const float* W2       = (const float*)d_in[7];
    const float* b2       = (const float*)d_in[8];
    float* out            = (float*)d_out;

    float *p_glimpse, *p_T, *p_part;
    int *p_idx, *p_cnt;
    cudaGetSymbolAddress((void**)&p_glimpse, g_glimpse);
    cudaGetSymbolAddress((void**)&p_T, g_T);
    cudaGetSymbolAddress((void**)&p_part, g_part);
    cudaGetSymbolAddress((void**)&p_idx, g_idx);
    cudaGetSymbolAddress((void**)&p_cnt, g_cnt);

    const int BH = Bb / 2;               // 128 per half
    const int BA = 32;                   // logits h0 part A (hidden early)
    const int BB = BH - BA;              // 96: part B covers ffn(h1) compute
    const size_t zc = (size_t)Bb * Esz;  // split-K z-stride in g_part

    cudaStream_t s2;
    cudaStreamCreateWithFlags(&s2, cudaStreamNonBlocking);
    cudaEvent_t evA0, evT, evB;
    cudaEventCreateWithFlags(&evA0, cudaEventDisableTiming);
    cudaEventCreateWithFlags(&evT, cudaEventDisableTiming);
    cudaEventCreateWithFlags(&evB, cudaEventDisableTiming);

    // -- compaction, then attention halves (main stream) --
    compact_kernel<<<Bb, 256>>>(mask, p_idx, p_cnt);
    attn_kernel<<<dim3(4, BH), 256>>>(query, key, value, p_idx, p_cnt,
                                      p_glimpse, 0);
    cudaEventRecord(evA0, 0);
    attn_kernel<<<dim3(4, BH), 256>>>(query, key, value, p_idx, p_cnt,
                                      p_glimpse, BH);
    cudaEventRecord(evT, 0);

    // -- half 0 FFN + logits part A on forked stream (hidden under attn h1) --
    cudaStreamWaitEvent(s2, evA0, 0);
    gemm_kernel<16, 32, 32, 2, 2, 128, 0>
        <<<dim3(DFFsz / 32, BH / 16, 1), 128, 0, s2>>>(
            p_glimpse, W1, p_T, b1, BH, DFFsz, Esz, Esz, 0);
    gemm_kernel<32, 32, 32, 2, 2, 256, 2>
        <<<dim3(Esz / 32, BH / 32, SPLITK), 256, 0, s2>>>(
            p_T, W2, p_part, nullptr, BH, Esz, DFFsz / SPLITK, DFFsz, zc);
    logits_kernel<<<dim3(2, BA), 512, 0, s2>>>(p_part, p_glimpse, b2,
                                               logitkey, out, 0);

    // -- half 0 logits part B: deferred until attn h1 done (covers ffn h1) --
    cudaStreamWaitEvent(s2, evT, 0);
    logits_kernel<<<dim3(2, BB), 512, 0, s2>>>(p_part, p_glimpse, b2,
                                               logitkey, out, BA);
    cudaEventRecord(evB, s2);

    // -- half 1 FFN + logits on main stream --
    gemm_kernel<16, 32, 32, 2, 2, 128, 0>
        <<<dim3(DFFsz / 32, BH / 16, 1), 128>>>(
            p_glimpse + (size_t)BH * Esz, W1, p_T + (size_t)BH * DFFsz, b1,
            BH, DFFsz, Esz, Esz, 0);
    gemm_kernel<32, 32, 32, 2, 2, 256, 2>
        <<<dim3(Esz / 32, BH / 32, SPLITK), 256>>>(
            p_T + (size_t)BH * DFFsz, W2, p_part + (size_t)BH * Esz, nullptr,
            BH, Esz, DFFsz / SPLITK, DFFsz, zc);
    logits_kernel<<<dim3(2, BH), 512>>>(p_part, p_glimpse, b2,
                                        logitkey, out, BH);

    // join
    cudaStreamWaitEvent(0, evB, 0);
}

// round 15
// speedup vs baseline: 1.1960x; 1.1960x over previous
#include <cuda_runtime.h>
#include <cuda_bf16.h>

#define Bb    256
#define Ssz   1000
#define Esz   512
#define Hh    8
#define DFFsz 2048
#define SPLITK 16
#define IDXPAD 1024
#define NEG_BIG (-1e30f)

// Scratch (device globals: allocation-free)
__device__ float g_glimpse[Bb * Esz];
__device__ float g_T[Bb * DFFsz];
__device__ float g_part[SPLITK * Bb * Esz];

// ---------------------------------------------------------------------------
// Kernel 1: attention over mask-compacted active rows, compaction fused
// in-kernel (each CTA scans its batch's mask into smem; deterministic order).
// Grid (4 E-chunks, nB), 256 threads (8 warps). 2 heads per CTA. 8-row unroll.
// ---------------------------------------------------------------------------
__global__ __launch_bounds__(256) void attn_kernel(
    const float* __restrict__ q,
    const float* __restrict__ kk,
    const float* __restrict__ vv,
    const int*   __restrict__ mask,   // [B, S]
    float* __restrict__ glimpse,
    int b0)
{
    __shared__ float qs[128];
    __shared__ int   idx_s[IDXPAD];
    __shared__ float sc[2][IDXPAD];
    __shared__ float wacc[8][128];
    __shared__ float red[2][4];
    __shared__ float invs[2];
    __shared__ int   wsum[8];
    __shared__ int   woff[8];
    __shared__ int   cn_s;

    const int hp   = blockIdx.x;
    const int b    = b0 + blockIdx.y;
    const int tid  = threadIdx.x;
    const int wid  = tid >> 5;
    const int lane = tid & 31;
    const int e0   = hp * 128;

    if (tid < 128) qs[tid] = q[b * Esz + e0 + tid];

    // ---- Fused compaction: ordered scan of mask into idx_s ----
    {
        const int* mb = mask + b * Ssz;
        const int s0 = tid * 4;
        int m[4];
        int c = 0;
        #pragma unroll
        for (int j = 0; j < 4; j++) {
            int s = s0 + j;
            m[j] = (s < Ssz) ? (mb[s] != 0) : 0;
            c += m[j];
        }
        int inc = c;
        #pragma unroll
        for (int o = 1; o < 32; o <<= 1) {
            int v = __shfl_up_sync(0xffffffffu, inc, o);
            if (lane >= o) inc += v;
        }
        if (lane == 31) wsum[wid] = inc;
        __syncthreads();
        if (tid == 0) {
            int acc = 0;
            #pragma unroll
            for (int w = 0; w < 8; w++) { woff[w] = acc; acc += wsum[w]; }
            cn_s = acc;
        }
        __syncthreads();
        int off = woff[wid] + inc - c;
        #pragma unroll
        for (int j = 0; j < 4; j++) {
            if (m[j]) idx_s[off++] = s0 + j;
        }
        __syncthreads();
        const int total = cn_s;
        const int pcl = (total + 63) & ~63;
        const int first = idx_s[0];    // >=1 active guaranteed
        for (int i = total + tid; i < pcl; i += 256) idx_s[i] = first;
    }
    __syncthreads();

    const int cn = cn_s;
    const int pc = (cn + 63) & ~63;

    const float4* q4 = (const float4*)qs;
    const float* kb = kk + (size_t)b * Ssz * Esz + e0;
    const float* vb = vv + (size_t)b * Ssz * Esz + e0;

    // ---- Pass A ----
    {
        const float4 qq = q4[lane];
        for (int i0 = wid * 8; i0 < pc; i0 += 64) {
            int s0 = idx_s[i0 + 0], s1 = idx_s[i0 + 1];
            int s2 = idx_s[i0 + 2], s3 = idx_s[i0 + 3];
            int s4 = idx_s[i0 + 4], s5 = idx_s[i0 + 5];
            int s6 = idx_s[i0 + 6], s7 = idx_s[i0 + 7];
            float4 k0 = __ldcs((const float4*)(kb + (size_t)s0 * Esz) + lane);
            float4 k1 = __ldcs((const float4*)(kb + (size_t)s1 * Esz) + lane);
            float4 k2 = __ldcs((const float4*)(kb + (size_t)s2 * Esz) + lane);
            float4 k3 = __ldcs((const float4*)(kb + (size_t)s3 * Esz) + lane);
            float4 k4 = __ldcs((const float4*)(kb + (size_t)s4 * Esz) + lane);
            float4 k5 = __ldcs((const float4*)(kb + (size_t)s5 * Esz) + lane);
            float4 k6 = __ldcs((const float4*)(kb + (size_t)s6 * Esz) + lane);
            float4 k7 = __ldcs((const float4*)(kb + (size_t)s7 * Esz) + lane);
            float p0 = k0.x * qq.x + k0.y * qq.y + k0.z * qq.z + k0.w * qq.w;
            float p1 = k1.x * qq.x + k1.y * qq.y + k1.z * qq.z + k1.w * qq.w;
            float p2 = k2.x * qq.x + k2.y * qq.y + k2.z * qq.z + k2.w * qq.w;
            float p3 = k3.x * qq.x + k3.y * qq.y + k3.z * qq.z + k3.w * qq.w;
            float p4 = k4.x * qq.x + k4.y * qq.y + k4.z * qq.z + k4.w * qq.w;
            float p5 = k5.x * qq.x + k5.y * qq.y + k5.z * qq.z + k5.w * qq.w;
            float p6 = k6.x * qq.x + k6.y * qq.y + k6.z * qq.z + k6.w * qq.w;
            float p7 = k7.x * qq.x + k7.y * qq.y + k7.z * qq.z + k7.w * qq.w;
            #pragma unroll
            for (int o = 1; o < 16; o <<= 1) {
                p0 += __shfl_xor_sync(0xffffffffu, p0, o);
                p1 += __shfl_xor_sync(0xffffffffu, p1, o);
                p2 += __shfl_xor_sync(0xffffffffu, p2, o);
                p3 += __shfl_xor_sync(0xffffffffu, p3, o);
                p4 += __shfl_xor_sync(0xffffffffu, p4, o);
                p5 += __shfl_xor_sync(0xffffffffu, p5, o);
                p6 += __shfl_xor_sync(0xffffffffu, p6, o);
                p7 += __shfl_xor_sync(0xffffffffu, p7, o);
            }
            if ((lane & 15) == 0) {
                int h = lane >> 4;
                sc[h][i0]     = p0 * 0.125f;
                sc[h][i0 + 1] = p1 * 0.125f;
                sc[h][i0 + 2] = p2 * 0.125f;
                sc[h][i0 + 3] = p3 * 0.125f;
                sc[h][i0 + 4] = p4 * 0.125f;
                sc[h][i0 + 5] = p5 * 0.125f;
                sc[h][i0 + 6] = p6 * 0.125f;
                sc[h][i0 + 7] = p7 * 0.125f;
            }
        }
    }
    __syncthreads();

    // ---- Softmax over [0, cn) ----
    {
        const int h = wid >> 2;
        const int sub = wid & 3;
        const int t = sub * 32 + lane;

        float m = NEG_BIG;
        for (int i = t; i < cn; i += 128) m = fmaxf(m, sc[h][i]);
        #pragma unroll
        for (int o = 16; o; o >>= 1) m = fmaxf(m, __shfl_xor_sync(0xffffffffu, m, o));
        if (lane == 0) red[h][sub] = m;
        __syncthreads();
        m = fmaxf(fmaxf(red[h][0], red[h][1]), fmaxf(red[h][2], red[h][3]));
        __syncthreads();

        float sum = 0.f;
        for (int i = t; i < cn; i += 128) {
            float e = __expf(sc[h][i] - m);
            sc[h][i] = e;
            sum += e;
        }
        #pragma unroll
        for (int o = 16; o; o >>= 1) sum += __shfl_xor_sync(0xffffffffu, sum, o);
        if (lane == 0) red[h][sub] = sum;
        __syncthreads();
        if (t == 0)
            invs[h] = 1.0f / (red[h][0] + red[h][1] + red[h][2] + red[h][3]);
    }
    for (int i = cn + tid; i < pc; i += 256) { sc[0][i] = 0.f; sc[1][i] = 0.f; }
    __syncthreads();

    // ---- Pass B ----
    {
        const int h = lane >> 4;
        float a0 = 0.f, a1 = 0.f, a2 = 0.f, a3 = 0.f;
        for (int i0 = wid * 8; i0 < pc; i0 += 64) {
            int s0 = idx_s[i0 + 0], s1 = idx_s[i0 + 1];
            int s2 = idx_s[i0 + 2], s3 = idx_s[i0 + 3];
            int s4 = idx_s[i0 + 4], s5 = idx_s[i0 + 5];
            int s6 = idx_s[i0 + 6], s7 = idx_s[i0 + 7];
            float4 v0 = __ldcs((const float4*)(vb + (size_t)s0 * Esz) + lane);
            float4 v1 = __ldcs((const float4*)(vb + (size_t)s1 * Esz) + lane);
            float4 v2 = __ldcs((const float4*)(vb + (size_t)s2 * Esz) + lane);
            float4 v3 = __ldcs((const float4*)(vb + (size_t)s3 * Esz) + lane);
            float4 v4 = __ldcs((const float4*)(vb + (size_t)s4 * Esz) + lane);
            float4 v5 = __ldcs((const float4*)(vb + (size_t)s5 * Esz) + lane);
            float4 v6 = __ldcs((const float4*)(vb + (size_t)s6 * Esz) + lane);
            float4 v7 = __ldcs((const float4*)(vb + (size_t)s7 * Esz) + lane);
            float p0 = sc[h][i0];
            float p1 = sc[h][i0 + 1];
            float p2 = sc[h][i0 + 2];
            float p3 = sc[h][i0 + 3];
            float p4 = sc[h][i0 + 4];
            float p5 = sc[h][i0 + 5];
            float p6 = sc[h][i0 + 6];
            float p7 = sc[h][i0 + 7];
            a0 += p0 * v0.x + p1 * v1.x + p2 * v2.x + p3 * v3.x
                + p4 * v4.x + p5 * v5.x + p6 * v6.x + p7 * v7.x;
            a1 += p0 * v0.y + p1 * v1.y + p2 * v2.y + p3 * v3.y
                + p4 * v4.y + p5 * v5.y + p6 * v6.y + p7 * v7.y;
            a2 += p0 * v0.z + p1 * v1.z + p2 * v2.z + p3 * v3.z
                + p4 * v4.z + p5 * v5.z + p6 * v6.z + p7 * v7.z;
            a3 += p0 * v0.w + p1 * v1.w + p2 * v2.w + p3 * v3.w
                + p4 * v4.w + p5 * v5.w + p6 * v6.w + p7 * v7.w;
        }
        float inv = invs[h];
        ((float4*)wacc[wid])[lane] = make_float4(a0 * inv, a1 * inv, a2 * inv, a3 * inv);
    }
    __syncthreads();

    if (tid < 128) {
        float r = 0.f;
        #pragma unroll
        for (int w = 0; w < 8; w++) r += wacc[w][tid];
        glimpse[b * Esz + e0 + tid] = r + qs[tid];
    }
}

// ---------------------------------------------------------------------------
// Double-buffered fp32 GEMM. EPI 0: relu(x+bias) -> C ; EPI 2: raw -> C
// blockIdx.z = split-K slice: A += z*K (cols), B += z*K*N, C += z*zc.
// ---------------------------------------------------------------------------
template <int BM, int BN, int BK, int TM, int TN, int NT, int EPI>
__global__ __launch_bounds__(NT) void gemm_kernel(
    const float* __restrict__ A, const float* __restrict__ B,
    float* __restrict__ C, const float* __restrict__ bias,
    int M, int N, int K, int lda, size_t zc)
{
    constexpr int PAD = 4;
    __shared__ float As[2][BK][BM + PAD];   // transposed [k][m]
    __shared__ float Bs[2][BK][BN];

    constexpr int TX = BN / TN;
    constexpr int KQ = BK / 4;
    constexpr int NQ = BN / 4;
    constexpr int AV = (BM * KQ) / NT;
    constexpr int BV = (BK * NQ) / NT;
    static_assert(AV * NT == BM * KQ && BV * NT == BK * NQ, "loaders");
    static_assert(TX * (BM / TM) == NT, "tiling");

    const int tid = threadIdx.x;
    const int tx = tid % TX;
    const int ty = tid / TX;
    const int m0 = blockIdx.y * BM;
    const int n0 = blockIdx.x * BN;
    const int z  = blockIdx.z;

    A += (size_t)z * K;
    B += (size_t)z * K * N;
    C += (size_t)z * zc;

    float acc[TM][TN];
    #pragma unroll
    for (int i = 0; i < TM; i++)
        #pragma unroll
        for (int j = 0; j < TN; j++) acc[i][j] = 0.f;

    #pragma unroll
    for (int r = 0; r < AV; r++) {
        int u = tid + r * NT, m = u / KQ, kq = u % KQ;
        float4 a = *(const float4*)&A[(size_t)(m0 + m) * lda + kq * 4];
        As[0][kq * 4 + 0][m] = a.x; As[0][kq * 4 + 1][m] = a.y;
        As[0][kq * 4 + 2][m] = a.z; As[0][kq * 4 + 3][m] = a.w;
    }
    #pragma unroll
    for (int r = 0; r < BV; r++) {
        int u = tid + r * NT, kr = u / NQ, nq = u % NQ;
        *(float4*)&Bs[0][kr][nq * 4] = *(const float4*)&B[(size_t)kr * N + n0 + nq * 4];
    }
    __syncthreads();

    const int nk = K / BK;
    float4 pa[AV], pb[BV];

    for (int t = 0; t < nk; t++) {
        const int cur = t & 1;
        if (t + 1 < nk) {
            const int k0 = (t + 1) * BK;
            #pragma unroll
            for (int r = 0; r < AV; r++) {
                int u = tid + r * NT, m = u / KQ, kq = u % KQ;
                pa[r] = *(const float4*)&A[(size_t)(m0 + m) * lda + k0 + kq * 4];
            }
            #pragma unroll
            for (int r = 0; r < BV; r++) {
                int u = tid + r * NT, kr = u / NQ, nq = u % NQ;
                pb[r] = *(const float4*)&B[(size_t)(k0 + kr) * N + n0 + nq * 4];
            }
        }
        #pragma unroll
        for (int k = 0; k < BK; k++) {
            float ra[TM], rb[TN];
            if constexpr (TM == 4) {
                float4 t4 = *(const float4*)&As[cur][k][ty * 4];
                ra[0] = t4.x; ra[1] = t4.y; ra[2] = t4.z; ra[3] = t4.w;
            } else {
                float2 t2 = *(const float2*)&As[cur][k][ty * 2];
                ra[0] = t2.x; ra[1] = t2.y;
            }
            if constexpr (TN == 4) {
                float4 t4 = *(const float4*)&Bs[cur][k][tx * 4];
                rb[0] = t4.x; rb[1] = t4.y; rb[2] = t4.z; rb[3] = t4.w;
            } else {
                float2 t2 = *(const float2*)&Bs[cur][k][tx * 2];
                rb[0] = t2.x; rb[1] = t2.y;
            }
            #pragma unroll
            for (int i = 0; i < TM; i++)
                #pragma unroll
                for (int j = 0; j < TN; j++) acc[i][j] += ra[i] * rb[j];
        }
        if (t + 1 < nk) {
            const int nb = cur ^ 1;
            #pragma unroll
            for (int r = 0; r < AV; r++) {
                int u = tid + r * NT, m = u / KQ, kq = u % KQ;
                As[nb][kq * 4 + 0][m] = pa[r].x; As[nb][kq * 4 + 1][m] = pa[r].y;
                As[nb][kq * 4 + 2][m] = pa[r].z; As[nb][kq * 4 + 3][m] = pa[r].w;
            }
            #pragma unroll
            for (int r = 0; r < BV; r++) {
                int u = tid + r * NT, kr = u / NQ, nq = u % NQ;
                *(float4*)&Bs[nb][kr][nq * 4] = pb[r];
            }
        }
        __syncthreads();
    }

    #pragma unroll
    for (int i = 0; i < TM; i++) {
        const int m = m0 + ty * TM + i;
        if constexpr (EPI == 0) {
            if constexpr (TN == 4) {
                float4 bs4 = *(const float4*)&bias[n0 + tx * 4];
                float4 o;
                o.x = fmaxf(acc[i][0] + bs4.x, 0.f);
                o.y = fmaxf(acc[i][1] + bs4.y, 0.f);
                o.z = fmaxf(acc[i][2] + bs4.z, 0.f);
                o.w = fmaxf(acc[i][3] + bs4.w, 0.f);
                *(float4*)&C[(size_t)m * N + n0 + tx * 4] = o;
            } else {
                float2 bs2 = *(const float2*)&bias[n0 + tx * 2];
                float2 o;
                o.x = fmaxf(acc[i][0] + bs2.x, 0.f);
                o.y = fmaxf(acc[i][1] + bs2.y, 0.f);
                *(float2*)&C[(size_t)m * N + n0 + tx * 2] = o;
            }
        } else {
            if constexpr (TN == 4) {
                float4 o;
                o.x = acc[i][0]; o.y = acc[i][1]; o.z = acc[i][2]; o.w = acc[i][3];
                *(float4*)&C[(size_t)m * N + n0 + tx * 4] = o;
            } else {
                float2 o; o.x = acc[i][0]; o.y = acc[i][1];
                *(float2*)&C[(size_t)m * N + n0 + tx * 2] = o;
            }
        }
    }
}

// ---------------------------------------------------------------------------
// Kernel 3: fused split-K reduce + pointer logits for batches [b0, ...).
// ---------------------------------------------------------------------------
__global__ __launch_bounds__(512) void logits_kernel(
    const float* __restrict__ part,
    const float* __restrict__ glimpse,
    const float* __restrict__ b2,
    const float* __restrict__ lk,
    float* __restrict__ out,
    int b0)
{
    __shared__ float gs[Esz];
    const int b    = b0 + blockIdx.y;
    const int tid  = threadIdx.x;
    const int wid  = tid >> 5;
    const int lane = tid & 31;

    {
        const int e = tid;
        float v = glimpse[b * Esz + e] + b2[e];
        #pragma unroll
        for (int z = 0; z < SPLITK; z++)
            v += part[(size_t)z * Bb * Esz + b * Esz + e];
        gs[e] = v;
    }
    __syncthreads();

    const float4* g4 = (const float4*)gs;
    const int s0 = blockIdx.x * 500;
    const float rscale = 0.04419417382415922f;  // 1/sqrt(512)

    for (int g = wid; g < 125; g += 16) {
        const int s = s0 + g * 4;
        const float4* r = (const float4*)(lk + ((size_t)b * Ssz + s) * Esz) + lane;
        float p0 = 0.f, p1 = 0.f, p2 = 0.f, p3 = 0.f;
        #pragma unroll
        for (int j = 0; j < 4; j++) {
            float4 qv = g4[j * 32 + lane];
            float4 a0 = __ldcs(r + j * 32);
            float4 a1 = __ldcs(r + 128 + j * 32);
            float4 a2 = __ldcs(r + 256 + j * 32);
            float4 a3 = __ldcs(r + 384 + j * 32);
            p0 += a0.x * qv.x + a0.y * qv.y + a0.z * qv.z + a0.w * qv.w;
            p1 += a1.x * qv.x + a1.y * qv.y + a1.z * qv.z + a1.w * qv.w;
            p2 += a2.x * qv.x + a2.y * qv.y + a2.z * qv.z + a2.w * qv.w;
            p3 += a3.x * qv.x + a3.y * qv.y + a3.z * qv.z + a3.w * qv.w;
        }
        #pragma unroll
        for (int o = 16; o; o >>= 1) {
            p0 += __shfl_xor_sync(0xffffffffu, p0, o);
            p1 += __shfl_xor_sync(0xffffffffu, p1, o);
            p2 += __shfl_xor_sync(0xffffffffu, p2, o);
            p3 += __shfl_xor_sync(0xffffffffu, p3, o);
        }
        if (lane == 0) {
            float4 o4 = make_float4(p0 * rscale, p1 * rscale, p2 * rscale, p3 * rscale);
            *(float4*)&out[(size_t)b * Ssz + s] = o4;
        }
    }
}

// ---------------------------------------------------------------------------
// Host: 2-half pipeline with balanced tail-fill (R12 schedule, fused compact).
// ---------------------------------------------------------------------------
extern "C" void kernel_launch(void* const* d_in, const int* in_sizes, int n_in,
                              void* d_out, int out_size)
{
    const float* query    = (const float*)d_in[0];
    const float* key      = (const float*)d_in[1];
    const float* value    = (const float*)d_in[2];
    const float* logitkey = (const float*)d_in[3];
    const int*   mask     = (const int*)  d_in[4];
    const float* W1       = (const float*)d_in[5];
    const float* b1       = (const float*)d_in[6];
    const float* W2       = (const float*)d_in[7];
    const float* b2       = (const float*)d_in[8];
    float* out            = (float*)d_out;

    float *p_glimpse, *p_T, *p_part;
    cudaGetSymbolAddress((void**)&p_glimpse, g_glimpse);
    cudaGetSymbolAddress((void**)&p_T, g_T);
    cudaGetSymbolAddress((void**)&p_part, g_part);

    const int BH = Bb / 2;               // 128 per half
    const int BA = 32;                   // logits h0 part A (hidden early)
    const int BB = BH - BA;              // 96: part B covers ffn(h1) compute
    const size_t zc = (size_t)Bb * Esz;  // split-K z-stride in g_part

    cudaStream_t s2;
    cudaStreamCreateWithFlags(&s2, cudaStreamNonBlocking);
    cudaEvent_t evA0, evT, evB;
    cudaEventCreateWithFlags(&evA0, cudaEventDisableTiming);
    cudaEventCreateWithFlags(&evT, cudaEventDisableTiming);
    cudaEventCreateWithFlags(&evB, cudaEventDisableTiming);

    // -- attention halves (main stream), compaction fused in-kernel --
    attn_kernel<<<dim3(4, BH), 256>>>(query, key, value, mask, p_glimpse, 0);
    cudaEventRecord(evA0, 0);
    attn_kernel<<<dim3(4, BH), 256>>>(query, key, value, mask, p_glimpse, BH);
    cudaEventRecord(evT, 0);

    // -- half 0 FFN + logits part A on forked stream (hidden under attn h1) --
    cudaStreamWaitEvent(s2, evA0, 0);
    gemm_kernel<32, 32, 32, 2, 2, 256, 0>
        <<<dim3(DFFsz / 32, BH / 32, 1), 256, 0, s2>>>(
            p_glimpse, W1, p_T, b1, BH, DFFsz, Esz, Esz, 0);
    gemm_kernel<32, 32, 32, 2, 2, 256, 2>
        <<<dim3(Esz / 32, BH / 32, SPLITK), 256, 0, s2>>>(
            p_T, W2, p_part, nullptr, BH, Esz, DFFsz / SPLITK, DFFsz, zc);
    logits_kernel<<<dim3(2, BA), 512, 0, s2>>>(p_part, p_glimpse, b2,
                                               logitkey, out, 0);

    // -- half 0 logits part B: deferred until attn h1 done (covers ffn h1) --
    cudaStreamWaitEvent(s2, evT, 0);
    logits_kernel<<<dim3(2, BB), 512, 0, s2>>>(p_part, p_glimpse, b2,
                                               logitkey, out, BA);
    cudaEventRecord(evB, s2);

    // -- half 1 FFN + logits on main stream --
    gemm_kernel<32, 32, 32, 2, 2, 256, 0>
        <<<dim3(DFFsz / 32, BH / 32, 1), 256>>>(
            p_glimpse + (size_t)BH * Esz, W1, p_T + (size_t)BH * DFFsz, b1,
            BH, DFFsz, Esz, Esz, 0);
    gemm_kernel<32, 32, 32, 2, 2, 256, 2>
        <<<dim3(Esz / 32, BH / 32, SPLITK), 256>>>(
            p_T + (size_t)BH * DFFsz, W2, p_part + (size_t)BH * Esz, nullptr,
            BH, Esz, DFFsz / SPLITK, DFFsz, zc);
    logits_kernel<<<dim3(2, BH), 512>>>(p_part, p_glimpse, b2,
                                        logitkey, out, BH);

    // join
    cudaStreamWaitEvent(0, evB, 0);
}

// round 16
// speedup vs baseline: 1.2175x; 1.0180x over previous
#include <cuda_runtime.h>
#include <cuda_bf16.h>

#define Bb    256
#define Ssz   1000
#define Esz   512
#define Hh    8
#define DFFsz 2048
#define SPLITK 16
#define IDXPAD 1024
#define NEG_BIG (-1e30f)

// Scratch (device globals: allocation-free)
__device__ float g_glimpse[Bb * Esz];
__device__ float g_T[Bb * DFFsz];
__device__ float g_part[SPLITK * Bb * Esz];

// ---------------------------------------------------------------------------
// Kernel 1: attention over mask-compacted active rows, compaction fused
// in-kernel. Grid (4 E-chunks, nB), 256 threads (8 warps). 2 heads per CTA.
// 8-row unroll (empirical optimum).
// ---------------------------------------------------------------------------
__global__ __launch_bounds__(256) void attn_kernel(
    const float* __restrict__ q,
    const float* __restrict__ kk,
    const float* __restrict__ vv,
    const int*   __restrict__ mask,   // [B, S]
    float* __restrict__ glimpse,
    int b0)
{
    __shared__ float qs[128];
    __shared__ int   idx_s[IDXPAD];
    __shared__ float sc[2][IDXPAD];
    __shared__ float wacc[8][128];
    __shared__ float red[2][4];
    __shared__ float invs[2];
    __shared__ int   wsum[8];
    __shared__ int   woff[8];
    __shared__ int   cn_s;

    const int hp   = blockIdx.x;
    const int b    = b0 + blockIdx.y;
    const int tid  = threadIdx.x;
    const int wid  = tid >> 5;
    const int lane = tid & 31;
    const int e0   = hp * 128;

    if (tid < 128) qs[tid] = q[b * Esz + e0 + tid];

    // ---- Fused compaction: ordered scan of mask into idx_s ----
    {
        const int* mb = mask + b * Ssz;
        const int s0 = tid * 4;
        int m[4];
        int c = 0;
        #pragma unroll
        for (int j = 0; j < 4; j++) {
            int s = s0 + j;
            m[j] = (s < Ssz) ? (mb[s] != 0) : 0;
            c += m[j];
        }
        int inc = c;
        #pragma unroll
        for (int o = 1; o < 32; o <<= 1) {
            int v = __shfl_up_sync(0xffffffffu, inc, o);
            if (lane >= o) inc += v;
        }
        if (lane == 31) wsum[wid] = inc;
        __syncthreads();
        if (tid == 0) {
            int acc = 0;
            #pragma unroll
            for (int w = 0; w < 8; w++) { woff[w] = acc; acc += wsum[w]; }
            cn_s = acc;
        }
        __syncthreads();
        int off = woff[wid] + inc - c;
        #pragma unroll
        for (int j = 0; j < 4; j++) {
            if (m[j]) idx_s[off++] = s0 + j;
        }
        __syncthreads();
        const int total = cn_s;
        const int pcl = (total + 63) & ~63;
        const int first = idx_s[0];    // >=1 active guaranteed
        for (int i = total + tid; i < pcl; i += 256) idx_s[i] = first;
    }
    __syncthreads();

    const int cn = cn_s;
    const int pc = (cn + 63) & ~63;

    const float4* q4 = (const float4*)qs;
    const float* kb = kk + (size_t)b * Ssz * Esz + e0;
    const float* vb = vv + (size_t)b * Ssz * Esz + e0;

    // ---- Pass A ----
    {
        const float4 qq = q4[lane];
        for (int i0 = wid * 8; i0 < pc; i0 += 64) {
            int s0 = idx_s[i0 + 0], s1 = idx_s[i0 + 1];
            int s2 = idx_s[i0 + 2], s3 = idx_s[i0 + 3];
            int s4 = idx_s[i0 + 4], s5 = idx_s[i0 + 5];
            int s6 = idx_s[i0 + 6], s7 = idx_s[i0 + 7];
            float4 k0 = __ldcs((const float4*)(kb + (size_t)s0 * Esz) + lane);
            float4 k1 = __ldcs((const float4*)(kb + (size_t)s1 * Esz) + lane);
            float4 k2 = __ldcs((const float4*)(kb + (size_t)s2 * Esz) + lane);
            float4 k3 = __ldcs((const float4*)(kb + (size_t)s3 * Esz) + lane);
            float4 k4 = __ldcs((const float4*)(kb + (size_t)s4 * Esz) + lane);
            float4 k5 = __ldcs((const float4*)(kb + (size_t)s5 * Esz) + lane);
            float4 k6 = __ldcs((const float4*)(kb + (size_t)s6 * Esz) + lane);
            float4 k7 = __ldcs((const float4*)(kb + (size_t)s7 * Esz) + lane);
            float p0 = k0.x * qq.x + k0.y * qq.y + k0.z * qq.z + k0.w * qq.w;
            float p1 = k1.x * qq.x + k1.y * qq.y + k1.z * qq.z + k1.w * qq.w;
            float p2 = k2.x * qq.x + k2.y * qq.y + k2.z * qq.z + k2.w * qq.w;
            float p3 = k3.x * qq.x + k3.y * qq.y + k3.z * qq.z + k3.w * qq.w;
            float p4 = k4.x * qq.x + k4.y * qq.y + k4.z * qq.z + k4.w * qq.w;
            float p5 = k5.x * qq.x + k5.y * qq.y + k5.z * qq.z + k5.w * qq.w;
            float p6 = k6.x * qq.x + k6.y * qq.y + k6.z * qq.z + k6.w * qq.w;
            float p7 = k7.x * qq.x + k7.y * qq.y + k7.z * qq.z + k7.w * qq.w;
            #pragma unroll
            for (int o = 1; o < 16; o <<= 1) {
                p0 += __shfl_xor_sync(0xffffffffu, p0, o);
                p1 += __shfl_xor_sync(0xffffffffu, p1, o);
                p2 += __shfl_xor_sync(0xffffffffu, p2, o);
                p3 += __shfl_xor_sync(0xffffffffu, p3, o);
                p4 += __shfl_xor_sync(0xffffffffu, p4, o);
                p5 += __shfl_xor_sync(0xffffffffu, p5, o);
                p6 += __shfl_xor_sync(0xffffffffu, p6, o);
                p7 += __shfl_xor_sync(0xffffffffu, p7, o);
            }
            if ((lane & 15) == 0) {
                int h = lane >> 4;
                sc[h][i0]     = p0 * 0.125f;
                sc[h][i0 + 1] = p1 * 0.125f;
                sc[h][i0 + 2] = p2 * 0.125f;
                sc[h][i0 + 3] = p3 * 0.125f;
                sc[h][i0 + 4] = p4 * 0.125f;
                sc[h][i0 + 5] = p5 * 0.125f;
                sc[h][i0 + 6] = p6 * 0.125f;
                sc[h][i0 + 7] = p7 * 0.125f;
            }
        }
    }
    __syncthreads();

    // ---- Softmax over [0, cn) ----
    {
        const int h = wid >> 2;
        const int sub = wid & 3;
        const int t = sub * 32 + lane;

        float m = NEG_BIG;
        for (int i = t; i < cn; i += 128) m = fmaxf(m, sc[h][i]);
        #pragma unroll
        for (int o = 16; o; o >>= 1) m = fmaxf(m, __shfl_xor_sync(0xffffffffu, m, o));
        if (lane == 0) red[h][sub] = m;
        __syncthreads();
        m = fmaxf(fmaxf(red[h][0], red[h][1]), fmaxf(red[h][2], red[h][3]));
        __syncthreads();

        float sum = 0.f;
        for (int i = t; i < cn; i += 128) {
            float e = __expf(sc[h][i] - m);
            sc[h][i] = e;
            sum += e;
        }
        #pragma unroll
        for (int o = 16; o; o >>= 1) sum += __shfl_xor_sync(0xffffffffu, sum, o);
        if (lane == 0) red[h][sub] = sum;
        __syncthreads();
        if (t == 0)
            invs[h] = 1.0f / (red[h][0] + red[h][1] + red[h][2] + red[h][3]);
    }
    for (int i = cn + tid; i < pc; i += 256) { sc[0][i] = 0.f; sc[1][i] = 0.f; }
    __syncthreads();

    // ---- Pass B ----
    {
        const int h = lane >> 4;
        float a0 = 0.f, a1 = 0.f, a2 = 0.f, a3 = 0.f;
        for (int i0 = wid * 8; i0 < pc; i0 += 64) {
            int s0 = idx_s[i0 + 0], s1 = idx_s[i0 + 1];
            int s2 = idx_s[i0 + 2], s3 = idx_s[i0 + 3];
            int s4 = idx_s[i0 + 4], s5 = idx_s[i0 + 5];
            int s6 = idx_s[i0 + 6], s7 = idx_s[i0 + 7];
            float4 v0 = __ldcs((const float4*)(vb + (size_t)s0 * Esz) + lane);
            float4 v1 = __ldcs((const float4*)(vb + (size_t)s1 * Esz) + lane);
            float4 v2 = __ldcs((const float4*)(vb + (size_t)s2 * Esz) + lane);
            float4 v3 = __ldcs((const float4*)(vb + (size_t)s3 * Esz) + lane);
            float4 v4 = __ldcs((const float4*)(vb + (size_t)s4 * Esz) + lane);
            float4 v5 = __ldcs((const float4*)(vb + (size_t)s5 * Esz) + lane);
            float4 v6 = __ldcs((const float4*)(vb + (size_t)s6 * Esz) + lane);
            float4 v7 = __ldcs((const float4*)(vb + (size_t)s7 * Esz) + lane);
            float p0 = sc[h][i0];
            float p1 = sc[h][i0 + 1];
            float p2 = sc[h][i0 + 2];
            float p3 = sc[h][i0 + 3];
            float p4 = sc[h][i0 + 4];
            float p5 = sc[h][i0 + 5];
            float p6 = sc[h][i0 + 6];
            float p7 = sc[h][i0 + 7];
            a0 += p0 * v0.x + p1 * v1.x + p2 * v2.x + p3 * v3.x
                + p4 * v4.x + p5 * v5.x + p6 * v6.x + p7 * v7.x;
            a1 += p0 * v0.y + p1 * v1.y + p2 * v2.y + p3 * v3.y
                + p4 * v4.y + p5 * v5.y + p6 * v6.y + p7 * v7.y;
            a2 += p0 * v0.z + p1 * v1.z + p2 * v2.z + p3 * v3.z
                + p4 * v4.z + p5 * v5.z + p6 * v6.z + p7 * v7.z;
            a3 += p0 * v0.w + p1 * v1.w + p2 * v2.w + p3 * v3.w
                + p4 * v4.w + p5 * v5.w + p6 * v6.w + p7 * v7.w;
        }
        float inv = invs[h];
        ((float4*)wacc[wid])[lane] = make_float4(a0 * inv, a1 * inv, a2 * inv, a3 * inv);
    }
    __syncthreads();

    if (tid < 128) {
        float r = 0.f;
        #pragma unroll
        for (int w = 0; w < 8; w++) r += wacc[w][tid];
        glimpse[b * Esz + e0 + tid] = r + qs[tid];
    }
}

// ---------------------------------------------------------------------------
// Double-buffered fp32 GEMM. EPI 0: relu(x+bias) -> C ; EPI 2: raw -> C
// blockIdx.z = split-K slice: A += z*K (cols), B += z*K*N, C += z*zc.
// ---------------------------------------------------------------------------
template <int BM, int BN, int BK, int TM, int TN, int NT, int EPI>
__global__ __launch_bounds__(NT) void gemm_kernel(
    const float* __restrict__ A, const float* __restrict__ B,
    float* __restrict__ C, const float* __restrict__ bias,
    int M, int N, int K, int lda, size_t zc)
{
    constexpr int PAD = 4;
    __shared__ float As[2][BK][BM + PAD];   // transposed [k][m]
    __shared__ float Bs[2][BK][BN];

    constexpr int TX = BN / TN;
    constexpr int KQ = BK / 4;
    constexpr int NQ = BN / 4;
    constexpr int AV = (BM * KQ) / NT;
    constexpr int BV = (BK * NQ) / NT;
    static_assert(AV * NT == BM * KQ && BV * NT == BK * NQ, "loaders");
    static_assert(TX * (BM / TM) == NT, "tiling");

    const int tid = threadIdx.x;
    const int tx = tid % TX;
    const int ty = tid / TX;
    const int m0 = blockIdx.y * BM;
    const int n0 = blockIdx.x * BN;
    const int z  = blockIdx.z;

    A += (size_t)z * K;
    B += (size_t)z * K * N;
    C += (size_t)z * zc;

    float acc[TM][TN];
    #pragma unroll
    for (int i = 0; i < TM; i++)
        #pragma unroll
        for (int j = 0; j < TN; j++) acc[i][j] = 0.f;

    #pragma unroll
    for (int r = 0; r < AV; r++) {
        int u = tid + r * NT, m = u / KQ, kq = u % KQ;
        float4 a = *(const float4*)&A[(size_t)(m0 + m) * lda + kq * 4];
        As[0][kq * 4 + 0][m] = a.x; As[0][kq * 4 + 1][m] = a.y;
        As[0][kq * 4 + 2][m] = a.z; As[0][kq * 4 + 3][m] = a.w;
    }
    #pragma unroll
    for (int r = 0; r < BV; r++) {
        int u = tid + r * NT, kr = u / NQ, nq = u % NQ;
        *(float4*)&Bs[0][kr][nq * 4] = *(const float4*)&B[(size_t)kr * N + n0 + nq * 4];
    }
    __syncthreads();

    const int nk = K / BK;
    float4 pa[AV], pb[BV];

    for (int t = 0; t < nk; t++) {
        const int cur = t & 1;
        if (t + 1 < nk) {
            const int k0 = (t + 1) * BK;
            #pragma unroll
            for (int r = 0; r < AV; r++) {
                int u = tid + r * NT, m = u / KQ, kq = u % KQ;
                pa[r] = *(const float4*)&A[(size_t)(m0 + m) * lda + k0 + kq * 4];
            }
            #pragma unroll
            for (int r = 0; r < BV; r++) {
                int u = tid + r * NT, kr = u / NQ, nq = u % NQ;
                pb[r] = *(const float4*)&B[(size_t)(k0 + kr) * N + n0 + nq * 4];
            }
        }
        #pragma unroll
        for (int k = 0; k < BK; k++) {
            float ra[TM], rb[TN];
            if constexpr (TM == 4) {
                float4 t4 = *(const float4*)&As[cur][k][ty * 4];
                ra[0] = t4.x; ra[1] = t4.y; ra[2] = t4.z; ra[3] = t4.w;
            } else {
                float2 t2 = *(const float2*)&As[cur][k][ty * 2];
                ra[0] = t2.x; ra[1] = t2.y;
            }
            if constexpr (TN == 4) {
                float4 t4 = *(const float4*)&Bs[cur][k][tx * 4];
                rb[0] = t4.x; rb[1] = t4.y; rb[2] = t4.z; rb[3] = t4.w;
            } else {
                float2 t2 = *(const float2*)&Bs[cur][k][tx * 2];
                rb[0] = t2.x; rb[1] = t2.y;
            }
            #pragma unroll
            for (int i = 0; i < TM; i++)
                #pragma unroll
                for (int j = 0; j < TN; j++) acc[i][j] += ra[i] * rb[j];
        }
        if (t + 1 < nk) {
            const int nb = cur ^ 1;
            #pragma unroll
            for (int r = 0; r < AV; r++) {
                int u = tid + r * NT, m = u / KQ, kq = u % KQ;
                As[nb][kq * 4 + 0][m] = pa[r].x; As[nb][kq * 4 + 1][m] = pa[r].y;
                As[nb][kq * 4 + 2][m] = pa[r].z; As[nb][kq * 4 + 3][m] = pa[r].w;
            }
            #pragma unroll
            for (int r = 0; r < BV; r++) {
                int u = tid + r * NT, kr = u / NQ, nq = u % NQ;
                *(float4*)&Bs[nb][kr][nq * 4] = pb[r];
            }
        }
        __syncthreads();
    }

    #pragma unroll
    for (int i = 0; i < TM; i++) {
        const int m = m0 + ty * TM + i;
        if constexpr (EPI == 0) {
            if constexpr (TN == 4) {
                float4 bs4 = *(const float4*)&bias[n0 + tx * 4];
                float4 o;
                o.x = fmaxf(acc[i][0] + bs4.x, 0.f);
                o.y = fmaxf(acc[i][1] + bs4.y, 0.f);
                o.z = fmaxf(acc[i][2] + bs4.z, 0.f);
                o.w = fmaxf(acc[i][3] + bs4.w, 0.f);
                *(float4*)&C[(size_t)m * N + n0 + tx * 4] = o;
            } else {
                float2 bs2 = *(const float2*)&bias[n0 + tx * 2];
                float2 o;
                o.x = fmaxf(acc[i][0] + bs2.x, 0.f);
                o.y = fmaxf(acc[i][1] + bs2.y, 0.f);
                *(float2*)&C[(size_t)m * N + n0 + tx * 2] = o;
            }
        } else {
            if constexpr (TN == 4) {
                float4 o;
                o.x = acc[i][0]; o.y = acc[i][1]; o.z = acc[i][2]; o.w = acc[i][3];
                *(float4*)&C[(size_t)m * N + n0 + tx * 4] = o;
            } else {
                float2 o; o.x = acc[i][0]; o.y = acc[i][1];
                *(float2*)&C[(size_t)m * N + n0 + tx * 2] = o;
            }
        }
    }
}

// ---------------------------------------------------------------------------
// Kernel 3: fused split-K reduce + pointer logits for batches [b0, ...).
// ---------------------------------------------------------------------------
__global__ __launch_bounds__(512) void logits_kernel(
    const float* __restrict__ part,
    const float* __restrict__ glimpse,
    const float* __restrict__ b2,
    const float* __restrict__ lk,
    float* __restrict__ out,
    int b0)
{
    __shared__ float gs[Esz];
    const int b    = b0 + blockIdx.y;
    const int tid  = threadIdx.x;
    const int wid  = tid >> 5;
    const int lane = tid & 31;

    {
        const int e = tid;
        float v = glimpse[b * Esz + e] + b2[e];
        #pragma unroll
        for (int z = 0; z < SPLITK; z++)
            v += part[(size_t)z * Bb * Esz + b * Esz + e];
        gs[e] = v;
    }
    __syncthreads();

    const float4* g4 = (const float4*)gs;
    const int s0 = blockIdx.x * 500;
    const float rscale = 0.04419417382415922f;  // 1/sqrt(512)

    for (int g = wid; g < 125; g += 16) {
        const int s = s0 + g * 4;
        const float4* r = (const float4*)(lk + ((size_t)b * Ssz + s) * Esz) + lane;
        float p0 = 0.f, p1 = 0.f, p2 = 0.f, p3 = 0.f;
        #pragma unroll
        for (int j = 0; j < 4; j++) {
            float4 qv = g4[j * 32 + lane];
            float4 a0 = __ldcs(r + j * 32);
            float4 a1 = __ldcs(r + 128 + j * 32);
            float4 a2 = __ldcs(r + 256 + j * 32);
            float4 a3 = __ldcs(r + 384 + j * 32);
            p0 += a0.x * qv.x + a0.y * qv.y + a0.z * qv.z + a0.w * qv.w;
            p1 += a1.x * qv.x + a1.y * qv.y + a1.z * qv.z + a1.w * qv.w;
            p2 += a2.x * qv.x + a2.y * qv.y + a2.z * qv.z + a2.w * qv.w;
            p3 += a3.x * qv.x + a3.y * qv.y + a3.z * qv.z + a3.w * qv.w;
        }
        #pragma unroll
        for (int o = 16; o; o >>= 1) {
            p0 += __shfl_xor_sync(0xffffffffu, p0, o);
            p1 += __shfl_xor_sync(0xffffffffu, p1, o);
            p2 += __shfl_xor_sync(0xffffffffu, p2, o);
            p3 += __shfl_xor_sync(0xffffffffu, p3, o);
        }
        if (lane == 0) {
            float4 o4 = make_float4(p0 * rscale, p1 * rscale, p2 * rscale, p3 * rscale);
            *(float4*)&out[(size_t)b * Ssz + s] = o4;
        }
    }
}

// ---------------------------------------------------------------------------
// Host: 2-half pipeline with balanced tail-fill (fused compact).
// ---------------------------------------------------------------------------
extern "C" void kernel_launch(void* const* d_in, const int* in_sizes, int n_in,
                              void* d_out, int out_size)
{
    const float* query    = (const float*)d_in[0];
    const float* key      = (const float*)d_in[1];
    const float* value    = (const float*)d_in[2];
    const float* logitkey = (const float*)d_in[3];
    const int*   mask     = (const int*)  d_in[4];
    const float* W1       = (const float*)d_in[5];
    const float* b1       = (const float*)d_in[6];
    const float* W2       = (const float*)d_in[7];
    const float* b2       = (const float*)d_in[8];
    float* out            = (float*)d_out;

    float *p_glimpse, *p_T, *p_part;
    cudaGetSymbolAddress((void**)&p_glimpse, g_glimpse);
    cudaGetSymbolAddress((void**)&p_T, g_T);
    cudaGetSymbolAddress((void**)&p_part, g_part);

    const int BH = Bb / 2;               // 128 per half
    const int BA = 32;                   // logits h0 part A (hidden early)
    const int BB = BH - BA;              // 96: part B covers ffn(h1) compute
    const size_t zc = (size_t)Bb * Esz;  // split-K z-stride in g_part

    cudaStream_t s2;
    cudaStreamCreateWithFlags(&s2, cudaStreamNonBlocking);
    cudaEvent_t evA0, evT, evB;
    cudaEventCreateWithFlags(&evA0, cudaEventDisableTiming);
    cudaEventCreateWithFlags(&evT, cudaEventDisableTiming);
    cudaEventCreateWithFlags(&evB, cudaEventDisableTiming);

    // -- attention halves (main stream), compaction fused in-kernel --
    attn_kernel<<<dim3(4, BH), 256>>>(query, key, value, mask, p_glimpse, 0);
    cudaEventRecord(evA0, 0);
    attn_kernel<<<dim3(4, BH), 256>>>(query, key, value, mask, p_glimpse, BH);
    cudaEventRecord(evT, 0);

    // -- half 0 FFN + logits part A on forked stream (hidden under attn h1) --
    cudaStreamWaitEvent(s2, evA0, 0);
    gemm_kernel<32, 32, 32, 2, 2, 256, 0>
        <<<dim3(DFFsz / 32, BH / 32, 1), 256, 0, s2>>>(
            p_glimpse, W1, p_T, b1, BH, DFFsz, Esz, Esz, 0);
    gemm_kernel<32, 64, 32, 2, 4, 256, 2>
        <<<dim3(Esz / 64, BH / 32, SPLITK), 256, 0, s2>>>(
            p_T, W2, p_part, nullptr, BH, Esz, DFFsz / SPLITK, DFFsz, zc);
    logits_kernel<<<dim3(2, BA), 512, 0, s2>>>(p_part, p_glimpse, b2,
                                               logitkey, out, 0);

    // -- half 0 logits part B: deferred until attn h1 done (covers ffn h1) --
    cudaStreamWaitEvent(s2, evT, 0);
    logits_kernel<<<dim3(2, BB), 512, 0, s2>>>(p_part, p_glimpse, b2,
                                               logitkey, out, BA);
    cudaEventRecord(evB, s2);

    // -- half 1 FFN + logits on main stream --
    gemm_kernel<32, 32, 32, 2, 2, 256, 0>
        <<<dim3(DFFsz / 32, BH / 32, 1), 256>>>(
            p_glimpse + (size_t)BH * Esz, W1, p_T + (size_t)BH * DFFsz, b1,
            BH, DFFsz, Esz, Esz, 0);
    gemm_kernel<32, 64, 32, 2, 4, 256, 2>
        <<<dim3(Esz / 64, BH / 32, SPLITK), 256>>>(
            p_T + (size_t)BH * DFFsz, W2, p_part + (size_t)BH * Esz, nullptr,
            BH, Esz, DFFsz / SPLITK, DFFsz, zc);
    logits_kernel<<<dim3(2, BH), 512>>>(p_part, p_glimpse, b2,
                                        logitkey, out, BH);

    // join
    cudaStreamWaitEvent(0, evB, 0);
}